// round 1
// baseline (speedup 1.0000x reference)
#include <cuda_runtime.h>

#define BB   16
#define CC   128
#define C2   256
#define OUTC 128
#define HH   128
#define WW   128
#define HW   16384
#define KGH  64
#define BGH  32
#define WPEROUT 1152      /* C*3*3 */
#define WKTOT   147456    /* OUT*WPEROUT */

// ---- scratch (device globals; no allocation allowed) ----
__device__ float g_pooled[BB * C2];
__device__ float g_hk[BB * KGH];
__device__ float g_hb[BB * BGH];
__device__ float g_dynk[BB * WKTOT];
__device__ float g_dynb[BB * OUTC];
__device__ float g_enh[(size_t)BB * CC * HW];   // 134 MB fp32 intermediate

// ============================================================
// 1) global average pool over H,W of concat([ir, vi], axis=1)
//    grid = B*2C blocks, one channel plane each
// ============================================================
__global__ void pool_kernel(const float* __restrict__ ir, const float* __restrict__ vi) {
    int bc = blockIdx.x;            // 0..4095
    int b  = bc >> 8;
    int ch = bc & 255;
    const float* src = (ch < CC) ? ir + (size_t)(b * CC + ch) * HW
                                 : vi + (size_t)(b * CC + (ch - CC)) * HW;
    const float4* s4 = (const float4*)src;
    float sum = 0.f;
    for (int i = threadIdx.x; i < HW / 4; i += 256) {
        float4 v = s4[i];
        sum += v.x + v.y + v.z + v.w;
    }
    __shared__ float red[8];
    #pragma unroll
    for (int o = 16; o > 0; o >>= 1) sum += __shfl_down_sync(0xffffffffu, sum, o);
    if ((threadIdx.x & 31) == 0) red[threadIdx.x >> 5] = sum;
    __syncthreads();
    if (threadIdx.x == 0) {
        float t = 0.f;
        #pragma unroll
        for (int i = 0; i < 8; i++) t += red[i];
        g_pooled[b * C2 + ch] = t * (1.0f / HW);
    }
}

// ============================================================
// 2) hidden layers: hk = relu(pooled@kg_w1^T+b), hb likewise
//    grid = B, block = 128 (64 hk threads + 32 hb threads)
// ============================================================
__global__ void mlp1_kernel(const float* __restrict__ kg_w1, const float* __restrict__ kg_b1,
                            const float* __restrict__ bg_w1, const float* __restrict__ bg_b1) {
    int b = blockIdx.x;
    __shared__ float p[C2];
    for (int i = threadIdx.x; i < C2; i += 128) p[i] = g_pooled[b * C2 + i];
    __syncthreads();
    int t = threadIdx.x;
    if (t < KGH) {
        float acc = kg_b1[t];
        const float* w = kg_w1 + t * C2;
        for (int k = 0; k < C2; k++) acc = fmaf(p[k], w[k], acc);
        g_hk[b * KGH + t] = fmaxf(acc, 0.f);
    } else if (t < KGH + BGH) {
        int u = t - KGH;
        float acc = bg_b1[u];
        const float* w = bg_w1 + u * C2;
        for (int k = 0; k < C2; k++) acc = fmaf(p[k], w[k], acc);
        g_hb[b * BGH + u] = fmaxf(acc, 0.f);
    }
}

// ============================================================
// 3) dyn_k = hk @ kg_w2^T + kg_b2  -> [B, 147456]
//    grid = 576 blocks * 256 thr; each thread owns one weight
//    row j, streams it ONCE, computes all 16 batches
// ============================================================
__global__ void dynk_kernel(const float* __restrict__ kg_w2, const float* __restrict__ kg_b2) {
    int j = blockIdx.x * 256 + threadIdx.x;   // < 147456 exactly
    __shared__ float hk_s[BB * KGH];
    for (int i = threadIdx.x; i < BB * KGH; i += 256) hk_s[i] = g_hk[i];
    __syncthreads();
    float bias = kg_b2[j];
    float acc[BB];
    #pragma unroll
    for (int b = 0; b < BB; b++) acc[b] = bias;
    const float4* w4 = (const float4*)(kg_w2 + (size_t)j * KGH);
    for (int kk = 0; kk < KGH / 4; kk++) {
        float4 w = w4[kk];
        #pragma unroll
        for (int b = 0; b < BB; b++) {
            const float* h = hk_s + b * KGH + kk * 4;
            acc[b] += w.x * h[0] + w.y * h[1] + w.z * h[2] + w.w * h[3];
        }
    }
    #pragma unroll
    for (int b = 0; b < BB; b++) g_dynk[(size_t)b * WKTOT + j] = acc[b];
}

// ============================================================
// 4) dyn_b = hb @ bg_w2^T + bg_b2  -> [B, 128]
// ============================================================
__global__ void dynb_kernel(const float* __restrict__ bg_w2, const float* __restrict__ bg_b2) {
    int b = blockIdx.x, o = threadIdx.x;
    float acc = bg_b2[o];
    const float* w = bg_w2 + o * BGH;
    const float* h = g_hb + b * BGH;
    for (int k = 0; k < BGH; k++) acc = fmaf(w[k], h[k], acc);
    g_dynb[b * OUTC + o] = acc;
}

// ============================================================
// 5) enhance: enh[b,oc,p] = relu(BN(sum_k en_w[oc,k]*concat[b,k,p]))
//    per-b GEMM M=128, K=256, N=16384. Tile 128(oc) x 64(px),
//    8x4 register micro-tile per thread (256 threads).
// ============================================================
__global__ __launch_bounds__(256) void enh_kernel(
    const float* __restrict__ ir, const float* __restrict__ vi,
    const float* __restrict__ en_w, const float* __restrict__ gmma,
    const float* __restrict__ beta, const float* __restrict__ mean,
    const float* __restrict__ var) {
    int b  = blockIdx.y;
    int p0 = blockIdx.x * 64;
    int tid = threadIdx.x;
    int tx = tid & 15, ty = tid >> 4;
    __shared__ float As[8][128];
    __shared__ float Bs[8][64];
    float acc[8][4];
    #pragma unroll
    for (int i = 0; i < 8; i++)
        #pragma unroll
        for (int j = 0; j < 4; j++) acc[i][j] = 0.f;

    for (int k0 = 0; k0 < C2; k0 += 8) {
        #pragma unroll
        for (int i = 0; i < 4; i++) {
            int e = tid * 4 + i;
            int kk = e >> 7, oc = e & 127;
            As[kk][oc] = en_w[oc * C2 + k0 + kk];
        }
        #pragma unroll
        for (int i = 0; i < 2; i++) {
            int e = tid * 2 + i;
            int kk = e >> 6, pp = e & 63;
            int k = k0 + kk;
            const float* src = (k < CC) ? ir + (size_t)(b * CC + k) * HW
                                        : vi + (size_t)(b * CC + k - CC) * HW;
            Bs[kk][pp] = src[p0 + pp];
        }
        __syncthreads();
        #pragma unroll
        for (int kk = 0; kk < 8; kk++) {
            float a[8], bv[4];
            #pragma unroll
            for (int i = 0; i < 8; i++) a[i] = As[kk][ty * 8 + i];
            #pragma unroll
            for (int j = 0; j < 4; j++) bv[j] = Bs[kk][tx * 4 + j];
            #pragma unroll
            for (int i = 0; i < 8; i++)
                #pragma unroll
                for (int j = 0; j < 4; j++)
                    acc[i][j] = fmaf(a[i], bv[j], acc[i][j]);
        }
        __syncthreads();
    }
    #pragma unroll
    for (int i = 0; i < 8; i++) {
        int oc = ty * 8 + i;
        float inv = gmma[oc] * rsqrtf(var[oc] + 1e-5f);
        float sh  = beta[oc] - mean[oc] * inv;
        float4 v;
        v.x = fmaxf(fmaf(acc[i][0], inv, sh), 0.f);
        v.y = fmaxf(fmaf(acc[i][1], inv, sh), 0.f);
        v.z = fmaxf(fmaf(acc[i][2], inv, sh), 0.f);
        v.w = fmaxf(fmaf(acc[i][3], inv, sh), 0.f);
        *(float4*)&g_enh[(size_t)(b * CC + oc) * HW + p0 + tx * 4] = v;
    }
}

// ============================================================
// 6) per-sample dynamic 3x3 conv (pad 1) + bias
//    block = (b, 8-out-channel group, 32x32 spatial tile)
//    thread = 2x2 pixels x 8 oc = 32 accumulators
//    smem: 34x34 halo tile for current input channel + 72 weights
// ============================================================
__global__ __launch_bounds__(256) void dconv_kernel(float* __restrict__ out) {
    int b    = blockIdx.z;
    int og   = blockIdx.y;                 // 16 groups of 8 output channels
    int tile = blockIdx.x;                 // 16 tiles of 32x32
    int r0 = (tile >> 2) * 32;
    int c0 = (tile & 3) * 32;
    int tid = threadIdx.x;
    int tx = tid & 15, ty = tid >> 4;

    __shared__ float sT[34 * 34];
    __shared__ float sW[72];

    float acc[8][2][2];
    #pragma unroll
    for (int o = 0; o < 8; o++)
        #pragma unroll
        for (int i = 0; i < 2; i++)
            #pragma unroll
            for (int j = 0; j < 2; j++) acc[o][i][j] = 0.f;

    const float* enh_b = g_enh + (size_t)b * CC * HW;
    const float* wk    = g_dynk + (size_t)b * WKTOT + og * 8 * WPEROUT;

    for (int c = 0; c < CC; c++) {
        const float* src = enh_b + (size_t)c * HW;
        for (int e = tid; e < 34 * 34; e += 256) {
            int rr = e / 34, ccx = e - rr * 34;
            int gr = r0 - 1 + rr, gc = c0 - 1 + ccx;
            float v = 0.f;
            if ((unsigned)gr < 128u && (unsigned)gc < 128u) v = src[gr * WW + gc];
            sT[e] = v;
        }
        if (tid < 72) sW[tid] = wk[(tid / 9) * WPEROUT + c * 9 + (tid % 9)];
        __syncthreads();

        float p[4][4];
        #pragma unroll
        for (int i = 0; i < 4; i++)
            #pragma unroll
            for (int j = 0; j < 4; j++)
                p[i][j] = sT[(ty * 2 + i) * 34 + tx * 2 + j];

        #pragma unroll
        for (int oc = 0; oc < 8; oc++) {
            float w[9];
            #pragma unroll
            for (int t = 0; t < 9; t++) w[t] = sW[oc * 9 + t];
            #pragma unroll
            for (int py = 0; py < 2; py++)
                #pragma unroll
                for (int px = 0; px < 2; px++) {
                    float s = acc[oc][py][px];
                    #pragma unroll
                    for (int i = 0; i < 3; i++)
                        #pragma unroll
                        for (int j = 0; j < 3; j++)
                            s = fmaf(p[py + i][px + j], w[i * 3 + j], s);
                    acc[oc][py][px] = s;
                }
        }
        __syncthreads();
    }

    #pragma unroll
    for (int oc = 0; oc < 8; oc++) {
        int o = og * 8 + oc;
        float bias = g_dynb[b * OUTC + o];
        #pragma unroll
        for (int py = 0; py < 2; py++) {
            int h = r0 + ty * 2 + py;
            #pragma unroll
            for (int px = 0; px < 2; px++) {
                int w_ = c0 + tx * 2 + px;
                out[((size_t)(b * OUTC + o) * HH + h) * WW + w_] = acc[oc][py][px] + bias;
            }
        }
    }
}

// ============================================================
extern "C" void kernel_launch(void* const* d_in, const int* in_sizes, int n_in,
                              void* d_out, int out_size) {
    const float* ir    = (const float*)d_in[0];
    const float* vi    = (const float*)d_in[1];
    const float* kg_w1 = (const float*)d_in[2];
    const float* kg_b1 = (const float*)d_in[3];
    const float* kg_w2 = (const float*)d_in[4];
    const float* kg_b2 = (const float*)d_in[5];
    const float* bg_w1 = (const float*)d_in[6];
    const float* bg_b1 = (const float*)d_in[7];
    const float* bg_w2 = (const float*)d_in[8];
    const float* bg_b2 = (const float*)d_in[9];
    const float* en_w  = (const float*)d_in[10];
    const float* gmma  = (const float*)d_in[11];
    const float* beta  = (const float*)d_in[12];
    const float* mean  = (const float*)d_in[13];
    const float* var   = (const float*)d_in[14];
    float* out = (float*)d_out;

    pool_kernel<<<BB * C2, 256>>>(ir, vi);
    mlp1_kernel<<<BB, 128>>>(kg_w1, kg_b1, bg_w1, bg_b1);
    dynk_kernel<<<WKTOT / 256, 256>>>(kg_w2, kg_b2);
    dynb_kernel<<<BB, OUTC>>>(bg_w2, bg_b2);
    enh_kernel<<<dim3(HW / 64, BB), 256>>>(ir, vi, en_w, gmma, beta, mean, var);
    dconv_kernel<<<dim3(16, 16, BB), 256>>>(out);
}